// round 4
// baseline (speedup 1.0000x reference)
#include <cuda_runtime.h>
#include <cstdint>

#define MAX_N 50000
#define MAX_E 1600000
#define CH    128   // hidden/out channels

// ---------------- scratch (static device globals; no runtime allocation) ----
__device__ float g_deg [MAX_N];
__device__ float g_dinv[MAX_N];
__device__ float g_norm[MAX_E];
__device__ float g_h   [(size_t)MAX_N * CH];
__device__ float g_agg [(size_t)MAX_N * CH];
__device__ float g_out1[(size_t)MAX_N * CH];

// ---------------- small utility kernels ------------------------------------
__global__ void init_deg_kernel(float* deg, int n) {
    int i = blockIdx.x * blockDim.x + threadIdx.x;
    if (i < n) deg[i] = 1.0f;   // self-loop contributes 1
}

__global__ void count_deg_kernel(const int* __restrict__ dst, float* deg, int E) {
    int i = blockIdx.x * blockDim.x + threadIdx.x;
    if (i < E) atomicAdd(&deg[dst[i]], 1.0f);
}

__global__ void dinv_kernel(const float* __restrict__ deg, float* dinv, int n) {
    int i = blockIdx.x * blockDim.x + threadIdx.x;
    if (i < n) dinv[i] = rsqrtf(deg[i]);
}

__global__ void norm_kernel(const int* __restrict__ src, const int* __restrict__ dst,
                            const float* __restrict__ dinv, float* norm, int E) {
    int i = blockIdx.x * blockDim.x + threadIdx.x;
    if (i < E) norm[i] = dinv[src[i]] * dinv[dst[i]];
}

// init agg with the self-loop + bias term: agg = h * dinv^2 + b
__global__ void agg_init_kernel(const float* __restrict__ h,
                                const float* __restrict__ dinv,
                                const float* __restrict__ b,
                                float* __restrict__ agg, int n)
{
    int i = blockIdx.x * blockDim.x + threadIdx.x;   // over n*32 float4s
    if (i >= n * 32) return;
    int node = i >> 5;
    int c4   = i & 31;
    float di = dinv[node];
    float dd = di * di;
    float4 hv = *(const float4*)(h + (size_t)i * 4);
    float4 bv = *(const float4*)(b + c4 * 4);
    float4 o;
    o.x = fmaf(hv.x, dd, bv.x);
    o.y = fmaf(hv.y, dd, bv.y);
    o.z = fmaf(hv.z, dd, bv.z);
    o.w = fmaf(hv.w, dd, bv.w);
    *(float4*)(agg + (size_t)i * 4) = o;
}

// ---------------- GEMM: C[M,128] = A[M,K] * W[K,128] ------------------------
// BM=64, BN=128, BK=32. 256 threads. warp = rows warp*8..+7, lane = cols lane*4..+3.
__global__ __launch_bounds__(256) void gemm_n128_kernel(
    const float* __restrict__ A, const float* __restrict__ W,
    float* __restrict__ C, int M, int K)
{
    __shared__ float As[32][68];   // [k][m], pad 68 keeps 16B alignment per row
    __shared__ float Bs[32][128];  // [k][n]

    const int tid  = threadIdx.x;
    const int warp = tid >> 5;
    const int lane = tid & 31;
    const int m0   = blockIdx.x * 64;

    float acc[8][4];
    #pragma unroll
    for (int i = 0; i < 8; i++)
        #pragma unroll
        for (int j = 0; j < 4; j++) acc[i][j] = 0.f;

    const int lr = tid >> 3;   // A-tile: row within tile (0..31), +32 for 2nd
    const int lc = tid & 7;    // A-tile: float4 column (0..7)

    for (int k0 = 0; k0 < K; k0 += 32) {
        // A tile: 64 rows x 32 k, stored transposed As[k][m]
        #pragma unroll
        for (int rr = lr; rr < 64; rr += 32) {
            float4 v = make_float4(0.f, 0.f, 0.f, 0.f);
            int grow = m0 + rr;
            if (grow < M)
                v = *(const float4*)(A + (size_t)grow * K + k0 + lc * 4);
            As[lc * 4 + 0][rr] = v.x;
            As[lc * 4 + 1][rr] = v.y;
            As[lc * 4 + 2][rr] = v.z;
            As[lc * 4 + 3][rr] = v.w;
        }
        // W tile: 32 rows x 128 cols (1024 float4, 4 per thread)
        #pragma unroll
        for (int i = 0; i < 4; i++) {
            int idx = tid + i * 256;
            int wr = idx >> 5, wc = idx & 31;
            *(float4*)&Bs[wr][wc * 4] =
                *(const float4*)(W + (size_t)(k0 + wr) * 128 + wc * 4);
        }
        __syncthreads();

        #pragma unroll
        for (int k = 0; k < 32; k++) {
            float4 a0 = *(const float4*)&As[k][warp * 8];
            float4 a1 = *(const float4*)&As[k][warp * 8 + 4];
            float4 b  = *(const float4*)&Bs[k][lane * 4];
            float a[8] = {a0.x, a0.y, a0.z, a0.w, a1.x, a1.y, a1.z, a1.w};
            float bb[4] = {b.x, b.y, b.z, b.w};
            #pragma unroll
            for (int i = 0; i < 8; i++)
                #pragma unroll
                for (int j = 0; j < 4; j++)
                    acc[i][j] = fmaf(a[i], bb[j], acc[i][j]);
        }
        __syncthreads();
    }

    #pragma unroll
    for (int i = 0; i < 8; i++) {
        int row = m0 + warp * 8 + i;
        if (row < M) {
            float4 v = make_float4(acc[i][0], acc[i][1], acc[i][2], acc[i][3]);
            *(float4*)(C + (size_t)row * 128 + lane * 4) = v;
        }
    }
}

// ---------------- scatter: agg[dst] += h[src] * norm ------------------------
// one warp per edge; each lane handles 4 channels via vector red.
__global__ __launch_bounds__(256) void scatter_kernel(
    const int* __restrict__ src, const int* __restrict__ dst,
    const float* __restrict__ norm, const float* __restrict__ h,
    float* __restrict__ agg, int E)
{
    int gw   = blockIdx.x * 8 + (threadIdx.x >> 5);
    int lane = threadIdx.x & 31;
    if (gw >= E) return;
    int   s = __ldg(&src[gw]);
    int   d = __ldg(&dst[gw]);
    float w = __ldg(&norm[gw]);
    float4 v = *(const float4*)(h + (size_t)s * 128 + lane * 4);
    float x0 = v.x * w, x1 = v.y * w, x2 = v.z * w, x3 = v.w * w;
    float* p = agg + (size_t)d * 128 + lane * 4;
#if __CUDA_ARCH__ >= 900
    asm volatile("red.global.add.v4.f32 [%0], {%1,%2,%3,%4};"
                 :: "l"(p), "f"(x0), "f"(x1), "f"(x2), "f"(x3) : "memory");
#else
    atomicAdd(p + 0, x0); atomicAdd(p + 1, x1);
    atomicAdd(p + 2, x2); atomicAdd(p + 3, x3);
#endif
}

// ---------------- relu: out = max(agg, 0) -----------------------------------
__global__ void relu_kernel(const float* __restrict__ agg,
                            float* __restrict__ out, int n4)
{
    int i = blockIdx.x * blockDim.x + threadIdx.x;   // over float4s
    if (i >= n4) return;
    float4 v = *(const float4*)(agg + (size_t)i * 4);
    v.x = fmaxf(v.x, 0.f);
    v.y = fmaxf(v.y, 0.f);
    v.z = fmaxf(v.z, 0.f);
    v.w = fmaxf(v.w, 0.f);
    *(float4*)(out + (size_t)i * 4) = v;
}

// ---------------- launch ----------------------------------------------------
extern "C" void kernel_launch(void* const* d_in, const int* in_sizes, int n_in,
                              void* d_out, int out_size)
{
    const float* x    = (const float*)d_in[0];
    const int*   ei   = (const int*)  d_in[1];
    const float* W1   = (const float*)d_in[2];
    const float* b1   = (const float*)d_in[3];
    const float* W2   = (const float*)d_in[4];
    const float* b2   = (const float*)d_in[5];
    float*       out  = (float*)d_out;

    const int K1 = 256;
    const int N  = in_sizes[0] / K1;     // 50000
    const int E  = in_sizes[1] / 2;      // 1.6M
    const int*   src = ei;
    const int*   dst = ei + E;

    float *deg, *dinv, *nrm, *h, *agg, *out1;
    cudaGetSymbolAddress((void**)&deg,  g_deg);
    cudaGetSymbolAddress((void**)&dinv, g_dinv);
    cudaGetSymbolAddress((void**)&nrm,  g_norm);
    cudaGetSymbolAddress((void**)&h,    g_h);
    cudaGetSymbolAddress((void**)&agg,  g_agg);
    cudaGetSymbolAddress((void**)&out1, g_out1);

    const int T = 256;
    const int nFeat4 = N * 32;                 // float4 count of [N,128]

    // degrees + edge norms (layer-invariant)
    init_deg_kernel <<<(N + T - 1) / T, T>>>(deg, N);
    count_deg_kernel<<<(E + T - 1) / T, T>>>(dst, deg, E);
    dinv_kernel     <<<(N + T - 1) / T, T>>>(deg, dinv, N);
    norm_kernel     <<<(E + T - 1) / T, T>>>(src, dst, dinv, nrm, E);

    int gemm_blocks    = (N + 63) / 64;
    int scatter_blocks = (E + 7) / 8;

    // ---- layer 1 ----
    gemm_n128_kernel<<<gemm_blocks, 256>>>(x, W1, h, N, K1);
    agg_init_kernel <<<(nFeat4 + T - 1) / T, T>>>(h, dinv, b1, agg, N);
    scatter_kernel  <<<scatter_blocks, 256>>>(src, dst, nrm, h, agg, E);
    relu_kernel     <<<(nFeat4 + T - 1) / T, T>>>(agg, out1, nFeat4);

    // ---- layer 2 ----
    gemm_n128_kernel<<<gemm_blocks, 256>>>(out1, W2, h, N, 128);
    agg_init_kernel <<<(nFeat4 + T - 1) / T, T>>>(h, dinv, b2, agg, N);
    scatter_kernel  <<<scatter_blocks, 256>>>(src, dst, nrm, h, agg, E);
    relu_kernel     <<<(nFeat4 + T - 1) / T, T>>>(agg, out, nFeat4);
}

// round 6
// speedup vs baseline: 1.6850x; 1.6850x over previous
#include <cuda_runtime.h>
#include <cstdint>

#define MAX_N 50000
#define MAX_E 1600000
#define CH    128

// ---------------- scratch (static device globals) ---------------------------
__device__ int   g_cnt [MAX_N];        // in-degree counts (no self loop)
__device__ int   g_cur [MAX_N];        // bucket cursors
__device__ int   g_off [MAX_N + 1];    // CSR row offsets (by dst)
__device__ float g_dinv[MAX_N];
__device__ int2  g_edges[MAX_E];       // sorted by dst: (src, norm bits)
__device__ float g_h   [(size_t)MAX_N * CH];
__device__ float g_out1[(size_t)MAX_N * CH];

// ---------------- preprocessing ---------------------------------------------
__global__ void zero_cnt_kernel(int* cnt, int* cur, int n) {
    int i = blockIdx.x * blockDim.x + threadIdx.x;
    if (i < n) { cnt[i] = 0; cur[i] = 0; }
}

__global__ void count_kernel(const int* __restrict__ dst, int* cnt, int E) {
    int i = blockIdx.x * blockDim.x + threadIdx.x;
    if (i < E) atomicAdd(&cnt[dst[i]], 1);
}

__global__ void dinv_kernel(const int* __restrict__ cnt, float* dinv, int n) {
    int i = blockIdx.x * blockDim.x + threadIdx.x;
    if (i < n) dinv[i] = rsqrtf((float)cnt[i] + 1.0f);   // +1 self loop
}

// single-block chunked exclusive scan: off[0..n) exclusive, off[n] = total
__global__ void scan_kernel(const int* __restrict__ cnt, int* __restrict__ off, int n) {
    __shared__ int sh[1024];
    const int t = threadIdx.x;
    const int chunk = (n + 1023) / 1024;
    const int i0 = t * chunk;
    int s = 0;
    for (int j = 0; j < chunk; j++) {
        int i = i0 + j;
        if (i < n) s += cnt[i];
    }
    sh[t] = s;
    __syncthreads();
    // Hillis-Steele inclusive scan over 1024 partials
    for (int ofs = 1; ofs < 1024; ofs <<= 1) {
        int v = 0;
        if (t >= ofs) v = sh[t - ofs];
        __syncthreads();
        sh[t] += v;
        __syncthreads();
    }
    int ex = sh[t] - s;   // exclusive prefix of this chunk
    for (int j = 0; j < chunk; j++) {
        int i = i0 + j;
        if (i < n) { off[i] = ex; ex += cnt[i]; }
    }
    if (t == 1023) off[n] = sh[1023];
}

// bucket edges by dst; store (src, norm) interleaved
__global__ void fill_kernel(const int* __restrict__ src, const int* __restrict__ dst,
                            const float* __restrict__ dinv,
                            const int* __restrict__ off, int* __restrict__ cur,
                            int2* __restrict__ edges, int E)
{
    int e = blockIdx.x * blockDim.x + threadIdx.x;
    if (e >= E) return;
    int s = src[e], d = dst[e];
    float w = dinv[s] * dinv[d];
    int pos = off[d] + atomicAdd(&cur[d], 1);
    edges[pos] = make_int2(s, __float_as_int(w));
}

// ---------------- GEMM: C[M,128] = A[M,K] * W[K,128] ------------------------
__global__ __launch_bounds__(256) void gemm_n128_kernel(
    const float* __restrict__ A, const float* __restrict__ W,
    float* __restrict__ C, int M, int K)
{
    __shared__ float As[32][68];
    __shared__ float Bs[32][128];

    const int tid  = threadIdx.x;
    const int warp = tid >> 5;
    const int lane = tid & 31;
    const int m0   = blockIdx.x * 64;

    float acc[8][4];
    #pragma unroll
    for (int i = 0; i < 8; i++)
        #pragma unroll
        for (int j = 0; j < 4; j++) acc[i][j] = 0.f;

    const int lr = tid >> 3;
    const int lc = tid & 7;

    for (int k0 = 0; k0 < K; k0 += 32) {
        #pragma unroll
        for (int rr = lr; rr < 64; rr += 32) {
            float4 v = make_float4(0.f, 0.f, 0.f, 0.f);
            int grow = m0 + rr;
            if (grow < M)
                v = *(const float4*)(A + (size_t)grow * K + k0 + lc * 4);
            As[lc * 4 + 0][rr] = v.x;
            As[lc * 4 + 1][rr] = v.y;
            As[lc * 4 + 2][rr] = v.z;
            As[lc * 4 + 3][rr] = v.w;
        }
        #pragma unroll
        for (int i = 0; i < 4; i++) {
            int idx = tid + i * 256;
            int wr = idx >> 5, wc = idx & 31;
            *(float4*)&Bs[wr][wc * 4] =
                *(const float4*)(W + (size_t)(k0 + wr) * 128 + wc * 4);
        }
        __syncthreads();

        #pragma unroll
        for (int k = 0; k < 32; k++) {
            float4 a0 = *(const float4*)&As[k][warp * 8];
            float4 a1 = *(const float4*)&As[k][warp * 8 + 4];
            float4 b  = *(const float4*)&Bs[k][lane * 4];
            float a[8] = {a0.x, a0.y, a0.z, a0.w, a1.x, a1.y, a1.z, a1.w};
            float bb[4] = {b.x, b.y, b.z, b.w};
            #pragma unroll
            for (int i = 0; i < 8; i++)
                #pragma unroll
                for (int j = 0; j < 4; j++)
                    acc[i][j] = fmaf(a[i], bb[j], acc[i][j]);
        }
        __syncthreads();
    }

    #pragma unroll
    for (int i = 0; i < 8; i++) {
        int row = m0 + warp * 8 + i;
        if (row < M) {
            float4 v = make_float4(acc[i][0], acc[i][1], acc[i][2], acc[i][3]);
            *(float4*)(C + (size_t)row * 128 + lane * 4) = v;
        }
    }
}

// ---------------- gather-aggregate: out = relu(sum + h*dinv^2 + b) ----------
// one warp per dst node; lane handles 4 channels in registers.
__global__ __launch_bounds__(256) void gather_kernel(
    const float* __restrict__ h, const int2* __restrict__ edges,
    const int* __restrict__ off, const float* __restrict__ dinv,
    const float* __restrict__ bias, float* __restrict__ out, int N)
{
    int node = (blockIdx.x * blockDim.x + threadIdx.x) >> 5;
    int lane = threadIdx.x & 31;
    if (node >= N) return;

    float di = dinv[node];
    float dd = di * di;
    float4 hv = *(const float4*)(h + (size_t)node * CH + lane * 4);
    float4 bv = *(const float4*)(bias + lane * 4);
    float4 acc;
    acc.x = fmaf(hv.x, dd, bv.x);
    acc.y = fmaf(hv.y, dd, bv.y);
    acc.z = fmaf(hv.z, dd, bv.z);
    acc.w = fmaf(hv.w, dd, bv.w);

    int e  = __ldg(&off[node]);
    int e1 = __ldg(&off[node + 1]);

    for (; e + 1 < e1; e += 2) {
        int2 ev0 = __ldg(&edges[e]);
        int2 ev1 = __ldg(&edges[e + 1]);
        float4 v0 = *(const float4*)(h + (size_t)ev0.x * CH + lane * 4);
        float4 v1 = *(const float4*)(h + (size_t)ev1.x * CH + lane * 4);
        float w0 = __int_as_float(ev0.y);
        float w1 = __int_as_float(ev1.y);
        acc.x = fmaf(v0.x, w0, acc.x);
        acc.y = fmaf(v0.y, w0, acc.y);
        acc.z = fmaf(v0.z, w0, acc.z);
        acc.w = fmaf(v0.w, w0, acc.w);
        acc.x = fmaf(v1.x, w1, acc.x);
        acc.y = fmaf(v1.y, w1, acc.y);
        acc.z = fmaf(v1.z, w1, acc.z);
        acc.w = fmaf(v1.w, w1, acc.w);
    }
    if (e < e1) {
        int2 ev = __ldg(&edges[e]);
        float4 v = *(const float4*)(h + (size_t)ev.x * CH + lane * 4);
        float w = __int_as_float(ev.y);
        acc.x = fmaf(v.x, w, acc.x);
        acc.y = fmaf(v.y, w, acc.y);
        acc.z = fmaf(v.z, w, acc.z);
        acc.w = fmaf(v.w, w, acc.w);
    }

    acc.x = fmaxf(acc.x, 0.f);
    acc.y = fmaxf(acc.y, 0.f);
    acc.z = fmaxf(acc.z, 0.f);
    acc.w = fmaxf(acc.w, 0.f);
    *(float4*)(out + (size_t)node * CH + lane * 4) = acc;
}

// ---------------- launch ----------------------------------------------------
extern "C" void kernel_launch(void* const* d_in, const int* in_sizes, int n_in,
                              void* d_out, int out_size)
{
    const float* x   = (const float*)d_in[0];
    const int*   ei  = (const int*)  d_in[1];
    const float* W1  = (const float*)d_in[2];
    const float* b1  = (const float*)d_in[3];
    const float* W2  = (const float*)d_in[4];
    const float* b2  = (const float*)d_in[5];
    float*       out = (float*)d_out;

    const int K1 = 256;
    const int N  = in_sizes[0] / K1;   // 50000
    const int E  = in_sizes[1] / 2;    // 1.6M
    const int* src = ei;
    const int* dst = ei + E;

    int *cnt, *cur, *off;  float *dinv, *h, *out1;  int2* edges;
    cudaGetSymbolAddress((void**)&cnt,   g_cnt);
    cudaGetSymbolAddress((void**)&cur,   g_cur);
    cudaGetSymbolAddress((void**)&off,   g_off);
    cudaGetSymbolAddress((void**)&dinv,  g_dinv);
    cudaGetSymbolAddress((void**)&edges, g_edges);
    cudaGetSymbolAddress((void**)&h,     g_h);
    cudaGetSymbolAddress((void**)&out1,  g_out1);

    const int T = 256;

    // --- build CSR by dst (once; reused by both layers) ---
    zero_cnt_kernel<<<(N + T - 1) / T, T>>>(cnt, cur, N);
    count_kernel   <<<(E + T - 1) / T, T>>>(dst, cnt, E);
    dinv_kernel    <<<(N + T - 1) / T, T>>>(cnt, dinv, N);
    scan_kernel    <<<1, 1024>>>(cnt, off, N);
    fill_kernel    <<<(E + T - 1) / T, T>>>(src, dst, dinv, off, cur, edges, E);

    int gemm_blocks   = (N + 63) / 64;
    int gather_blocks = (N + 7) / 8;   // 8 warps (nodes) per 256-thread block

    // ---- layer 1 ----
    gemm_n128_kernel<<<gemm_blocks, 256>>>(x, W1, h, N, K1);
    gather_kernel   <<<gather_blocks, 256>>>(h, edges, off, dinv, b1, out1, N);

    // ---- layer 2 ----
    gemm_n128_kernel<<<gemm_blocks, 256>>>(out1, W2, h, N, 128);
    gather_kernel   <<<gather_blocks, 256>>>(h, edges, off, dinv, b2, out, N);
}

// round 7
// speedup vs baseline: 2.0515x; 1.2175x over previous
#include <cuda_runtime.h>
#include <cstdint>

#define MAX_N 50000
#define MAX_E 1600000
#define CH    128

// ---------------- scratch (static device globals) ---------------------------
__device__ int   g_cnt [MAX_N];
__device__ int   g_cur [MAX_N];
__device__ int   g_off [MAX_N + 1];
__device__ int   g_part[256];
__device__ float g_dinv[MAX_N];
__device__ int2  g_edges[MAX_E];
__device__ float g_h   [(size_t)MAX_N * CH];
__device__ float g_out1[(size_t)MAX_N * CH];

// ---------------- preprocessing ---------------------------------------------
__global__ void zero_cnt_kernel(int* cnt, int* cur, int n) {
    int i = blockIdx.x * blockDim.x + threadIdx.x;
    if (i < n) { cnt[i] = 0; cur[i] = 0; }
}

__global__ void count_kernel(const int* __restrict__ dst, int* cnt, int E) {
    int i = blockIdx.x * blockDim.x + threadIdx.x;
    if (i < E) atomicAdd(&cnt[dst[i]], 1);
}

__global__ void dinv_kernel(const int* __restrict__ cnt, float* dinv, int n) {
    int i = blockIdx.x * blockDim.x + threadIdx.x;
    if (i < n) dinv[i] = rsqrtf((float)cnt[i] + 1.0f);   // +1 self loop
}

// --- 3-kernel scan: block partials -> scan partials -> write offsets --------
__global__ void scan_part_kernel(const int* __restrict__ cnt, int* __restrict__ part, int n) {
    __shared__ int sh[256];
    int b = blockIdx.x, t = threadIdx.x;
    int base = b * 1024 + t * 4;
    int s = 0;
    #pragma unroll
    for (int j = 0; j < 4; j++) if (base + j < n) s += cnt[base + j];
    sh[t] = s;
    __syncthreads();
    for (int o = 128; o > 0; o >>= 1) {
        if (t < o) sh[t] += sh[t + o];
        __syncthreads();
    }
    if (t == 0) part[b] = sh[0];
}

__global__ void scan_tops_kernel(int* part, int nb) {
    __shared__ int sh[128];
    int t = threadIdx.x;
    int v = (t < nb) ? part[t] : 0;
    sh[t] = v;
    __syncthreads();
    for (int o = 1; o < 128; o <<= 1) {
        int add = (t >= o) ? sh[t - o] : 0;
        __syncthreads();
        sh[t] += add;
        __syncthreads();
    }
    if (t < nb) part[t] = sh[t] - v;   // exclusive
}

__global__ void scan_write_kernel(const int* __restrict__ cnt, const int* __restrict__ part,
                                  int* __restrict__ off, int n, int E) {
    __shared__ int sh[256];
    int b = blockIdx.x, t = threadIdx.x;
    int base = b * 1024 + t * 4;
    int c[4]; int s = 0;
    #pragma unroll
    for (int j = 0; j < 4; j++) {
        c[j] = (base + j < n) ? cnt[base + j] : 0;
        s += c[j];
    }
    int v = s;
    sh[t] = s;
    __syncthreads();
    for (int o = 1; o < 256; o <<= 1) {
        int add = (t >= o) ? sh[t - o] : 0;
        __syncthreads();
        sh[t] += add;
        __syncthreads();
    }
    int ex = sh[t] - v + part[b];
    #pragma unroll
    for (int j = 0; j < 4; j++) {
        if (base + j < n) { off[base + j] = ex; ex += c[j]; }
    }
    if (b == 0 && t == 0) off[n] = E;
}

__global__ void fill_kernel(const int* __restrict__ src, const int* __restrict__ dst,
                            const float* __restrict__ dinv,
                            const int* __restrict__ off, int* __restrict__ cur,
                            int2* __restrict__ edges, int E)
{
    int e = blockIdx.x * blockDim.x + threadIdx.x;
    if (e >= E) return;
    int s = src[e], d = dst[e];
    float w = dinv[s] * dinv[d];
    int pos = off[d] + atomicAdd(&cur[d], 1);
    edges[pos] = make_int2(s, __float_as_int(w));
}

// ---------------- tensor-core GEMM (3xTF32): C[M,128] = A[M,K]*W[K,128] -----
// BM=64, BN=128, BK=32. 256 threads = 8 warps (2 warp_m x 4 warp_n), each warp
// computes 32x32 = 2 m16 x 4 n8 mma tiles.
__device__ __forceinline__ uint32_t f2tf32(float x) {
    uint32_t r;
    asm("cvt.rna.tf32.f32 %0, %1;" : "=r"(r) : "f"(x));
    return r;
}

__device__ __forceinline__ void mma_tf32(float* c, const uint32_t* a, const uint32_t* b) {
    asm volatile(
        "mma.sync.aligned.m16n8k8.row.col.f32.tf32.tf32.f32 "
        "{%0,%1,%2,%3}, {%4,%5,%6,%7}, {%8,%9}, {%0,%1,%2,%3};"
        : "+f"(c[0]), "+f"(c[1]), "+f"(c[2]), "+f"(c[3])
        : "r"(a[0]), "r"(a[1]), "r"(a[2]), "r"(a[3]), "r"(b[0]), "r"(b[1]));
}

#define AS_STRIDE 36    // conflict-free A frag reads
#define BS_STRIDE 136   // conflict-free B frag reads

__global__ __launch_bounds__(256) void gemm_tc_kernel(
    const float* __restrict__ A, const float* __restrict__ W,
    float* __restrict__ C, int M, int K)
{
    __shared__ float As[64][AS_STRIDE];
    __shared__ float Bs[32][BS_STRIDE];

    const int tid    = threadIdx.x;
    const int lane   = tid & 31;
    const int wid    = tid >> 5;
    const int warp_m = wid >> 2;      // 0..1
    const int warp_n = wid & 3;       // 0..3
    const int m0     = blockIdx.x * 64;

    float acc[2][4][4];
    #pragma unroll
    for (int i = 0; i < 2; i++)
        #pragma unroll
        for (int j = 0; j < 4; j++)
            #pragma unroll
            for (int k = 0; k < 4; k++) acc[i][j][k] = 0.f;

    const int ar  = tid >> 3;   // 0..31 (A tile row, +32 second)
    const int ac4 = tid & 7;    // A tile float4 col

    for (int k0 = 0; k0 < K; k0 += 32) {
        // A tile 64x32
        #pragma unroll
        for (int rr = ar; rr < 64; rr += 32) {
            float4 v = make_float4(0.f, 0.f, 0.f, 0.f);
            int grow = m0 + rr;
            if (grow < M)
                v = *(const float4*)(A + (size_t)grow * K + k0 + ac4 * 4);
            *(float4*)&As[rr][ac4 * 4] = v;
        }
        // B tile 32x128
        #pragma unroll
        for (int i = 0; i < 4; i++) {
            int idx = tid + i * 256;
            int wr = idx >> 5, wc = idx & 31;
            *(float4*)&Bs[wr][wc * 4] =
                *(const float4*)(W + (size_t)(k0 + wr) * 128 + wc * 4);
        }
        __syncthreads();

        #pragma unroll
        for (int ks = 0; ks < 4; ks++) {
            const int kc = ks * 8 + (lane & 3);
            // A fragments (2 m16 tiles), split hi/lo
            uint32_t ah[2][4], al[2][4];
            #pragma unroll
            for (int tm = 0; tm < 2; tm++) {
                int r0 = warp_m * 32 + tm * 16 + (lane >> 2);
                float f0 = As[r0][kc];
                float f1 = As[r0 + 8][kc];
                float f2 = As[r0][kc + 4];
                float f3 = As[r0 + 8][kc + 4];
                ah[tm][0] = f2tf32(f0); al[tm][0] = f2tf32(f0 - __uint_as_float(ah[tm][0]));
                ah[tm][1] = f2tf32(f1); al[tm][1] = f2tf32(f1 - __uint_as_float(ah[tm][1]));
                ah[tm][2] = f2tf32(f2); al[tm][2] = f2tf32(f2 - __uint_as_float(ah[tm][2]));
                ah[tm][3] = f2tf32(f3); al[tm][3] = f2tf32(f3 - __uint_as_float(ah[tm][3]));
            }
            // B fragments (4 n8 tiles), split hi/lo
            uint32_t bh[4][2], bl[4][2];
            #pragma unroll
            for (int tn = 0; tn < 4; tn++) {
                int nn = warp_n * 32 + tn * 8 + (lane >> 2);
                int kk = ks * 8 + (lane & 3);
                float f0 = Bs[kk][nn];
                float f1 = Bs[kk + 4][nn];
                bh[tn][0] = f2tf32(f0); bl[tn][0] = f2tf32(f0 - __uint_as_float(bh[tn][0]));
                bh[tn][1] = f2tf32(f1); bl[tn][1] = f2tf32(f1 - __uint_as_float(bh[tn][1]));
            }
            // 3xTF32 mma
            #pragma unroll
            for (int tm = 0; tm < 2; tm++)
                #pragma unroll
                for (int tn = 0; tn < 4; tn++) {
                    mma_tf32(acc[tm][tn], ah[tm], bl[tn]);
                    mma_tf32(acc[tm][tn], al[tm], bh[tn]);
                    mma_tf32(acc[tm][tn], ah[tm], bh[tn]);
                }
        }
        __syncthreads();
    }

    // store C
    #pragma unroll
    for (int tm = 0; tm < 2; tm++)
        #pragma unroll
        for (int tn = 0; tn < 4; tn++) {
            int row0 = m0 + warp_m * 32 + tm * 16 + (lane >> 2);
            int coln = warp_n * 32 + tn * 8 + (lane & 3) * 2;
            if (row0 < M) {
                float2 v0 = make_float2(acc[tm][tn][0], acc[tm][tn][1]);
                *(float2*)(C + (size_t)row0 * 128 + coln) = v0;
            }
            if (row0 + 8 < M) {
                float2 v1 = make_float2(acc[tm][tn][2], acc[tm][tn][3]);
                *(float2*)(C + (size_t)(row0 + 8) * 128 + coln) = v1;
            }
        }
}

// ---------------- gather-aggregate: out = relu(sum + h*dinv^2 + b) ----------
__global__ __launch_bounds__(256) void gather_kernel(
    const float* __restrict__ h, const int2* __restrict__ edges,
    const int* __restrict__ off, const float* __restrict__ dinv,
    const float* __restrict__ bias, float* __restrict__ out, int N)
{
    int node = (blockIdx.x * blockDim.x + threadIdx.x) >> 5;
    int lane = threadIdx.x & 31;
    if (node >= N) return;

    float di = dinv[node];
    float dd = di * di;
    float4 hv = *(const float4*)(h + (size_t)node * CH + lane * 4);
    float4 bv = *(const float4*)(bias + lane * 4);
    float4 acc;
    acc.x = fmaf(hv.x, dd, bv.x);
    acc.y = fmaf(hv.y, dd, bv.y);
    acc.z = fmaf(hv.z, dd, bv.z);
    acc.w = fmaf(hv.w, dd, bv.w);

    int e  = __ldg(&off[node]);
    int e1 = __ldg(&off[node + 1]);

    for (; e + 3 < e1; e += 4) {
        int2 ev0 = __ldg(&edges[e]);
        int2 ev1 = __ldg(&edges[e + 1]);
        int2 ev2 = __ldg(&edges[e + 2]);
        int2 ev3 = __ldg(&edges[e + 3]);
        float4 v0 = *(const float4*)(h + (size_t)ev0.x * CH + lane * 4);
        float4 v1 = *(const float4*)(h + (size_t)ev1.x * CH + lane * 4);
        float4 v2 = *(const float4*)(h + (size_t)ev2.x * CH + lane * 4);
        float4 v3 = *(const float4*)(h + (size_t)ev3.x * CH + lane * 4);
        float w0 = __int_as_float(ev0.y);
        float w1 = __int_as_float(ev1.y);
        float w2 = __int_as_float(ev2.y);
        float w3 = __int_as_float(ev3.y);
        acc.x = fmaf(v0.x, w0, acc.x); acc.y = fmaf(v0.y, w0, acc.y);
        acc.z = fmaf(v0.z, w0, acc.z); acc.w = fmaf(v0.w, w0, acc.w);
        acc.x = fmaf(v1.x, w1, acc.x); acc.y = fmaf(v1.y, w1, acc.y);
        acc.z = fmaf(v1.z, w1, acc.z); acc.w = fmaf(v1.w, w1, acc.w);
        acc.x = fmaf(v2.x, w2, acc.x); acc.y = fmaf(v2.y, w2, acc.y);
        acc.z = fmaf(v2.z, w2, acc.z); acc.w = fmaf(v2.w, w2, acc.w);
        acc.x = fmaf(v3.x, w3, acc.x); acc.y = fmaf(v3.y, w3, acc.y);
        acc.z = fmaf(v3.z, w3, acc.z); acc.w = fmaf(v3.w, w3, acc.w);
    }
    for (; e < e1; e++) {
        int2 ev = __ldg(&edges[e]);
        float4 v = *(const float4*)(h + (size_t)ev.x * CH + lane * 4);
        float w = __int_as_float(ev.y);
        acc.x = fmaf(v.x, w, acc.x); acc.y = fmaf(v.y, w, acc.y);
        acc.z = fmaf(v.z, w, acc.z); acc.w = fmaf(v.w, w, acc.w);
    }

    acc.x = fmaxf(acc.x, 0.f);
    acc.y = fmaxf(acc.y, 0.f);
    acc.z = fmaxf(acc.z, 0.f);
    acc.w = fmaxf(acc.w, 0.f);
    *(float4*)(out + (size_t)node * CH + lane * 4) = acc;
}

// ---------------- launch ----------------------------------------------------
extern "C" void kernel_launch(void* const* d_in, const int* in_sizes, int n_in,
                              void* d_out, int out_size)
{
    const float* x   = (const float*)d_in[0];
    const int*   ei  = (const int*)  d_in[1];
    const float* W1  = (const float*)d_in[2];
    const float* b1  = (const float*)d_in[3];
    const float* W2  = (const float*)d_in[4];
    const float* b2  = (const float*)d_in[5];
    float*       out = (float*)d_out;

    const int K1 = 256;
    const int N  = in_sizes[0] / K1;   // 50000
    const int E  = in_sizes[1] / 2;    // 1.6M
    const int* src = ei;
    const int* dst = ei + E;

    int *cnt, *cur, *off, *part;  float *dinv, *h, *out1;  int2* edges;
    cudaGetSymbolAddress((void**)&cnt,   g_cnt);
    cudaGetSymbolAddress((void**)&cur,   g_cur);
    cudaGetSymbolAddress((void**)&off,   g_off);
    cudaGetSymbolAddress((void**)&part,  g_part);
    cudaGetSymbolAddress((void**)&dinv,  g_dinv);
    cudaGetSymbolAddress((void**)&edges, g_edges);
    cudaGetSymbolAddress((void**)&h,     g_h);
    cudaGetSymbolAddress((void**)&out1,  g_out1);

    const int T  = 256;
    const int nb = (N + 1023) / 1024;   // scan blocks (<=128)

    // --- build CSR by dst (once; reused by both layers) ---
    zero_cnt_kernel  <<<(N + T - 1) / T, T>>>(cnt, cur, N);
    count_kernel     <<<(E + T - 1) / T, T>>>(dst, cnt, E);
    dinv_kernel      <<<(N + T - 1) / T, T>>>(cnt, dinv, N);
    scan_part_kernel <<<nb, 256>>>(cnt, part, N);
    scan_tops_kernel <<<1, 128>>>(part, nb);
    scan_write_kernel<<<nb, 256>>>(cnt, part, off, N, E);
    fill_kernel      <<<(E + T - 1) / T, T>>>(src, dst, dinv, off, cur, edges, E);

    int gemm_blocks   = (N + 63) / 64;
    int gather_blocks = (N + 7) / 8;

    // ---- layer 1 ----
    gemm_tc_kernel<<<gemm_blocks, 256>>>(x, W1, h, N, K1);
    gather_kernel <<<gather_blocks, 256>>>(h, edges, off, dinv, b1, out1, N);

    // ---- layer 2 ----
    gemm_tc_kernel<<<gemm_blocks, 256>>>(out1, W2, h, N, 128);
    gather_kernel <<<gather_blocks, 256>>>(h, edges, off, dinv, b2, out, N);
}

// round 8
// speedup vs baseline: 2.1027x; 1.0250x over previous
#include <cuda_runtime.h>
#include <cuda_fp16.h>
#include <cstdint>

#define MAX_N 50000
#define MAX_E 1600000
#define CH    128

// ---------------- scratch (static device globals) ---------------------------
__device__ int    g_cnt [MAX_N];
__device__ int    g_cur [MAX_N];
__device__ int    g_off [MAX_N + 1];
__device__ int    g_part[256];
__device__ float  g_dinv[MAX_N];
__device__ int2   g_edges[MAX_E];
__device__ float  g_h   [(size_t)MAX_N * CH];
__device__ __half g_hh  [(size_t)MAX_N * CH];   // fp16 mirror for edge gathers
__device__ float  g_out1[(size_t)MAX_N * CH];

// ---------------- preprocessing ---------------------------------------------
__global__ void zero_cnt_kernel(int* cnt, int* cur, int n) {
    int i = blockIdx.x * blockDim.x + threadIdx.x;
    if (i < n) { cnt[i] = 0; cur[i] = 0; }
}

__global__ void count_kernel(const int* __restrict__ dst, int* cnt, int E) {
    int i = blockIdx.x * blockDim.x + threadIdx.x;
    if (i < E) atomicAdd(&cnt[dst[i]], 1);
}

__global__ void dinv_kernel(const int* __restrict__ cnt, float* dinv, int n) {
    int i = blockIdx.x * blockDim.x + threadIdx.x;
    if (i < n) dinv[i] = rsqrtf((float)cnt[i] + 1.0f);   // +1 self loop
}

// --- 3-kernel scan: block partials -> scan partials -> write offsets --------
__global__ void scan_part_kernel(const int* __restrict__ cnt, int* __restrict__ part, int n) {
    __shared__ int sh[256];
    int b = blockIdx.x, t = threadIdx.x;
    int base = b * 1024 + t * 4;
    int s = 0;
    #pragma unroll
    for (int j = 0; j < 4; j++) if (base + j < n) s += cnt[base + j];
    sh[t] = s;
    __syncthreads();
    for (int o = 128; o > 0; o >>= 1) {
        if (t < o) sh[t] += sh[t + o];
        __syncthreads();
    }
    if (t == 0) part[b] = sh[0];
}

__global__ void scan_tops_kernel(int* part, int nb) {
    __shared__ int sh[128];
    int t = threadIdx.x;
    int v = (t < nb) ? part[t] : 0;
    sh[t] = v;
    __syncthreads();
    for (int o = 1; o < 128; o <<= 1) {
        int add = (t >= o) ? sh[t - o] : 0;
        __syncthreads();
        sh[t] += add;
        __syncthreads();
    }
    if (t < nb) part[t] = sh[t] - v;   // exclusive
}

__global__ void scan_write_kernel(const int* __restrict__ cnt, const int* __restrict__ part,
                                  int* __restrict__ off, int n, int E) {
    __shared__ int sh[256];
    int b = blockIdx.x, t = threadIdx.x;
    int base = b * 1024 + t * 4;
    int c[4]; int s = 0;
    #pragma unroll
    for (int j = 0; j < 4; j++) {
        c[j] = (base + j < n) ? cnt[base + j] : 0;
        s += c[j];
    }
    int v = s;
    sh[t] = s;
    __syncthreads();
    for (int o = 1; o < 256; o <<= 1) {
        int add = (t >= o) ? sh[t - o] : 0;
        __syncthreads();
        sh[t] += add;
        __syncthreads();
    }
    int ex = sh[t] - v + part[b];
    #pragma unroll
    for (int j = 0; j < 4; j++) {
        if (base + j < n) { off[base + j] = ex; ex += c[j]; }
    }
    if (b == 0 && t == 0) off[n] = E;
}

__global__ void fill_kernel(const int* __restrict__ src, const int* __restrict__ dst,
                            const float* __restrict__ dinv,
                            const int* __restrict__ off, int* __restrict__ cur,
                            int2* __restrict__ edges, int E)
{
    int e = blockIdx.x * blockDim.x + threadIdx.x;
    if (e >= E) return;
    int s = src[e], d = dst[e];
    float w = dinv[s] * dinv[d];
    int pos = off[d] + atomicAdd(&cur[d], 1);
    edges[pos] = make_int2(s, __float_as_int(w));
}

// ---------------- tensor-core GEMM (3xTF32): C[M,128] = A[M,K]*W[K,128] -----
__device__ __forceinline__ uint32_t f2tf32(float x) {
    uint32_t r;
    asm("cvt.rna.tf32.f32 %0, %1;" : "=r"(r) : "f"(x));
    return r;
}

__device__ __forceinline__ void mma_tf32(float* c, const uint32_t* a, const uint32_t* b) {
    asm volatile(
        "mma.sync.aligned.m16n8k8.row.col.f32.tf32.tf32.f32 "
        "{%0,%1,%2,%3}, {%4,%5,%6,%7}, {%8,%9}, {%0,%1,%2,%3};"
        : "+f"(c[0]), "+f"(c[1]), "+f"(c[2]), "+f"(c[3])
        : "r"(a[0]), "r"(a[1]), "r"(a[2]), "r"(a[3]), "r"(b[0]), "r"(b[1]));
}

#define AS_STRIDE 36
#define BS_STRIDE 136

__global__ __launch_bounds__(256) void gemm_tc_kernel(
    const float* __restrict__ A, const float* __restrict__ W,
    float* __restrict__ C, __half* __restrict__ Ch, int M, int K)
{
    __shared__ float As[64][AS_STRIDE];
    __shared__ float Bs[32][BS_STRIDE];

    const int tid    = threadIdx.x;
    const int lane   = tid & 31;
    const int wid    = tid >> 5;
    const int warp_m = wid >> 2;
    const int warp_n = wid & 3;
    const int m0     = blockIdx.x * 64;

    float acc[2][4][4];
    #pragma unroll
    for (int i = 0; i < 2; i++)
        #pragma unroll
        for (int j = 0; j < 4; j++)
            #pragma unroll
            for (int k = 0; k < 4; k++) acc[i][j][k] = 0.f;

    const int ar  = tid >> 3;
    const int ac4 = tid & 7;

    for (int k0 = 0; k0 < K; k0 += 32) {
        #pragma unroll
        for (int rr = ar; rr < 64; rr += 32) {
            float4 v = make_float4(0.f, 0.f, 0.f, 0.f);
            int grow = m0 + rr;
            if (grow < M)
                v = *(const float4*)(A + (size_t)grow * K + k0 + ac4 * 4);
            *(float4*)&As[rr][ac4 * 4] = v;
        }
        #pragma unroll
        for (int i = 0; i < 4; i++) {
            int idx = tid + i * 256;
            int wr = idx >> 5, wc = idx & 31;
            *(float4*)&Bs[wr][wc * 4] =
                *(const float4*)(W + (size_t)(k0 + wr) * 128 + wc * 4);
        }
        __syncthreads();

        #pragma unroll
        for (int ks = 0; ks < 4; ks++) {
            const int kc = ks * 8 + (lane & 3);
            uint32_t ah[2][4], al[2][4];
            #pragma unroll
            for (int tm = 0; tm < 2; tm++) {
                int r0 = warp_m * 32 + tm * 16 + (lane >> 2);
                float f0 = As[r0][kc];
                float f1 = As[r0 + 8][kc];
                float f2 = As[r0][kc + 4];
                float f3 = As[r0 + 8][kc + 4];
                ah[tm][0] = f2tf32(f0); al[tm][0] = f2tf32(f0 - __uint_as_float(ah[tm][0]));
                ah[tm][1] = f2tf32(f1); al[tm][1] = f2tf32(f1 - __uint_as_float(ah[tm][1]));
                ah[tm][2] = f2tf32(f2); al[tm][2] = f2tf32(f2 - __uint_as_float(ah[tm][2]));
                ah[tm][3] = f2tf32(f3); al[tm][3] = f2tf32(f3 - __uint_as_float(ah[tm][3]));
            }
            uint32_t bh[4][2], bl[4][2];
            #pragma unroll
            for (int tn = 0; tn < 4; tn++) {
                int nn = warp_n * 32 + tn * 8 + (lane >> 2);
                int kk = ks * 8 + (lane & 3);
                float f0 = Bs[kk][nn];
                float f1 = Bs[kk + 4][nn];
                bh[tn][0] = f2tf32(f0); bl[tn][0] = f2tf32(f0 - __uint_as_float(bh[tn][0]));
                bh[tn][1] = f2tf32(f1); bl[tn][1] = f2tf32(f1 - __uint_as_float(bh[tn][1]));
            }
            #pragma unroll
            for (int tm = 0; tm < 2; tm++)
                #pragma unroll
                for (int tn = 0; tn < 4; tn++) {
                    mma_tf32(acc[tm][tn], ah[tm], bl[tn]);
                    mma_tf32(acc[tm][tn], al[tm], bh[tn]);
                    mma_tf32(acc[tm][tn], ah[tm], bh[tn]);
                }
        }
        __syncthreads();
    }

    // store C (fp32) + Ch (fp16 mirror)
    #pragma unroll
    for (int tm = 0; tm < 2; tm++)
        #pragma unroll
        for (int tn = 0; tn < 4; tn++) {
            int row0 = m0 + warp_m * 32 + tm * 16 + (lane >> 2);
            int coln = warp_n * 32 + tn * 8 + (lane & 3) * 2;
            if (row0 < M) {
                *(float2*)(C + (size_t)row0 * 128 + coln) =
                    make_float2(acc[tm][tn][0], acc[tm][tn][1]);
                *(__half2*)(Ch + (size_t)row0 * 128 + coln) =
                    __floats2half2_rn(acc[tm][tn][0], acc[tm][tn][1]);
            }
            if (row0 + 8 < M) {
                *(float2*)(C + (size_t)(row0 + 8) * 128 + coln) =
                    make_float2(acc[tm][tn][2], acc[tm][tn][3]);
                *(__half2*)(Ch + (size_t)(row0 + 8) * 128 + coln) =
                    __floats2half2_rn(acc[tm][tn][2], acc[tm][tn][3]);
            }
        }
}

// ---------------- gather-aggregate: out = relu(sum + h*dinv^2 + b) ----------
// one warp per dst node; lane owns 4 channels; neighbors read from fp16 mirror.
__global__ __launch_bounds__(256) void gather_kernel(
    const float* __restrict__ h, const __half* __restrict__ hh,
    const int2* __restrict__ edges,
    const int* __restrict__ off, const float* __restrict__ dinv,
    const float* __restrict__ bias, float* __restrict__ out, int N)
{
    int node = (blockIdx.x * blockDim.x + threadIdx.x) >> 5;
    int lane = threadIdx.x & 31;
    if (node >= N) return;

    float di = dinv[node];
    float dd = di * di;
    float4 hv = *(const float4*)(h + (size_t)node * CH + lane * 4);
    float4 bv = *(const float4*)(bias + lane * 4);
    float4 acc;
    acc.x = fmaf(hv.x, dd, bv.x);
    acc.y = fmaf(hv.y, dd, bv.y);
    acc.z = fmaf(hv.z, dd, bv.z);
    acc.w = fmaf(hv.w, dd, bv.w);

    int e  = __ldg(&off[node]);
    int e1 = __ldg(&off[node + 1]);

    for (; e + 3 < e1; e += 4) {
        int2 ev0 = __ldg(&edges[e]);
        int2 ev1 = __ldg(&edges[e + 1]);
        int2 ev2 = __ldg(&edges[e + 2]);
        int2 ev3 = __ldg(&edges[e + 3]);
        __half2 p0 = *(const __half2*)(hh + (size_t)ev0.x * CH + lane * 4);
        __half2 q0 = *(const __half2*)(hh + (size_t)ev0.x * CH + lane * 4 + 2);
        __half2 p1 = *(const __half2*)(hh + (size_t)ev1.x * CH + lane * 4);
        __half2 q1 = *(const __half2*)(hh + (size_t)ev1.x * CH + lane * 4 + 2);
        __half2 p2 = *(const __half2*)(hh + (size_t)ev2.x * CH + lane * 4);
        __half2 q2 = *(const __half2*)(hh + (size_t)ev2.x * CH + lane * 4 + 2);
        __half2 p3 = *(const __half2*)(hh + (size_t)ev3.x * CH + lane * 4);
        __half2 q3 = *(const __half2*)(hh + (size_t)ev3.x * CH + lane * 4 + 2);
        float w0 = __int_as_float(ev0.y);
        float w1 = __int_as_float(ev1.y);
        float w2 = __int_as_float(ev2.y);
        float w3 = __int_as_float(ev3.y);
        float2 a0 = __half22float2(p0), b0 = __half22float2(q0);
        float2 a1 = __half22float2(p1), b1 = __half22float2(q1);
        float2 a2 = __half22float2(p2), b2 = __half22float2(q2);
        float2 a3 = __half22float2(p3), b3 = __half22float2(q3);
        acc.x = fmaf(a0.x, w0, acc.x); acc.y = fmaf(a0.y, w0, acc.y);
        acc.z = fmaf(b0.x, w0, acc.z); acc.w = fmaf(b0.y, w0, acc.w);
        acc.x = fmaf(a1.x, w1, acc.x); acc.y = fmaf(a1.y, w1, acc.y);
        acc.z = fmaf(b1.x, w1, acc.z); acc.w = fmaf(b1.y, w1, acc.w);
        acc.x = fmaf(a2.x, w2, acc.x); acc.y = fmaf(a2.y, w2, acc.y);
        acc.z = fmaf(b2.x, w2, acc.z); acc.w = fmaf(b2.y, w2, acc.w);
        acc.x = fmaf(a3.x, w3, acc.x); acc.y = fmaf(a3.y, w3, acc.y);
        acc.z = fmaf(b3.x, w3, acc.z); acc.w = fmaf(b3.y, w3, acc.w);
    }
    for (; e < e1; e++) {
        int2 ev = __ldg(&edges[e]);
        __half2 p = *(const __half2*)(hh + (size_t)ev.x * CH + lane * 4);
        __half2 q = *(const __half2*)(hh + (size_t)ev.x * CH + lane * 4 + 2);
        float w = __int_as_float(ev.y);
        float2 a = __half22float2(p), b = __half22float2(q);
        acc.x = fmaf(a.x, w, acc.x); acc.y = fmaf(a.y, w, acc.y);
        acc.z = fmaf(b.x, w, acc.z); acc.w = fmaf(b.y, w, acc.w);
    }

    acc.x = fmaxf(acc.x, 0.f);
    acc.y = fmaxf(acc.y, 0.f);
    acc.z = fmaxf(acc.z, 0.f);
    acc.w = fmaxf(acc.w, 0.f);
    *(float4*)(out + (size_t)node * CH + lane * 4) = acc;
}

// ---------------- launch ----------------------------------------------------
extern "C" void kernel_launch(void* const* d_in, const int* in_sizes, int n_in,
                              void* d_out, int out_size)
{
    const float* x   = (const float*)d_in[0];
    const int*   ei  = (const int*)  d_in[1];
    const float* W1  = (const float*)d_in[2];
    const float* b1  = (const float*)d_in[3];
    const float* W2  = (const float*)d_in[4];
    const float* b2  = (const float*)d_in[5];
    float*       out = (float*)d_out;

    const int K1 = 256;
    const int N  = in_sizes[0] / K1;   // 50000
    const int E  = in_sizes[1] / 2;    // 1.6M
    const int* src = ei;
    const int* dst = ei + E;

    int *cnt, *cur, *off, *part;  float *dinv, *h, *out1;  int2* edges;  __half* hh;
    cudaGetSymbolAddress((void**)&cnt,   g_cnt);
    cudaGetSymbolAddress((void**)&cur,   g_cur);
    cudaGetSymbolAddress((void**)&off,   g_off);
    cudaGetSymbolAddress((void**)&part,  g_part);
    cudaGetSymbolAddress((void**)&dinv,  g_dinv);
    cudaGetSymbolAddress((void**)&edges, g_edges);
    cudaGetSymbolAddress((void**)&h,     g_h);
    cudaGetSymbolAddress((void**)&hh,    g_hh);
    cudaGetSymbolAddress((void**)&out1,  g_out1);

    const int T  = 256;
    const int nb = (N + 1023) / 1024;

    // --- build CSR by dst (once; reused by both layers) ---
    zero_cnt_kernel  <<<(N + T - 1) / T, T>>>(cnt, cur, N);
    count_kernel     <<<(E + T - 1) / T, T>>>(dst, cnt, E);
    dinv_kernel      <<<(N + T - 1) / T, T>>>(cnt, dinv, N);
    scan_part_kernel <<<nb, 256>>>(cnt, part, N);
    scan_tops_kernel <<<1, 128>>>(part, nb);
    scan_write_kernel<<<nb, 256>>>(cnt, part, off, N, E);
    fill_kernel      <<<(E + T - 1) / T, T>>>(src, dst, dinv, off, cur, edges, E);

    int gemm_blocks   = (N + 63) / 64;
    int gather_blocks = (N + 7) / 8;

    // ---- layer 1 ----
    gemm_tc_kernel<<<gemm_blocks, 256>>>(x, W1, h, hh, N, K1);
    gather_kernel <<<gather_blocks, 256>>>(h, hh, edges, off, dinv, b1, out1, N);

    // ---- layer 2 ----
    gemm_tc_kernel<<<gemm_blocks, 256>>>(out1, W2, h, hh, N, 128);
    gather_kernel <<<gather_blocks, 256>>>(h, hh, edges, off, dinv, b2, out, N);
}

// round 12
// speedup vs baseline: 2.4113x; 1.1467x over previous
#include <cuda_runtime.h>
#include <cuda_fp16.h>
#include <cstdint>

#define MAX_N 50000
#define MAX_E 1600000
#define CH    128

// ---------------- scratch (static device globals) ---------------------------
__device__ int    g_cnt [MAX_N];
__device__ int    g_cur [MAX_N];
__device__ int    g_off [MAX_N + 1];
__device__ int    g_part[256];
__device__ float  g_dinv[MAX_N];
__device__ int2   g_edges[MAX_E];
__device__ float  g_h   [(size_t)MAX_N * CH];
__device__ __half g_hh  [(size_t)MAX_N * CH];   // fp16 mirror for edge gathers
__device__ float  g_out1[(size_t)MAX_N * CH];
// transposed + split weights: [N=128][K]
__device__ __half g_w1h[128 * 256];
__device__ __half g_w1l[128 * 256];
__device__ __half g_w2h[128 * 128];
__device__ __half g_w2l[128 * 128];

// ---------------- preprocessing ---------------------------------------------
__global__ void zero_cnt_kernel(int* cnt, int* cur, int n) {
    int i = blockIdx.x * blockDim.x + threadIdx.x;
    if (i < n) { cnt[i] = 0; cur[i] = 0; }
}

__global__ void count_kernel(const int* __restrict__ dst, int* cnt, int E) {
    int i = blockIdx.x * blockDim.x + threadIdx.x;
    if (i < E) atomicAdd(&cnt[dst[i]], 1);
}

__global__ void dinv_kernel(const int* __restrict__ cnt, float* dinv, int n) {
    int i = blockIdx.x * blockDim.x + threadIdx.x;
    if (i < n) dinv[i] = rsqrtf((float)cnt[i] + 1.0f);   // +1 self loop
}

__global__ void scan_part_kernel(const int* __restrict__ cnt, int* __restrict__ part, int n) {
    __shared__ int sh[256];
    int b = blockIdx.x, t = threadIdx.x;
    int base = b * 1024 + t * 4;
    int s = 0;
    #pragma unroll
    for (int j = 0; j < 4; j++) if (base + j < n) s += cnt[base + j];
    sh[t] = s;
    __syncthreads();
    for (int o = 128; o > 0; o >>= 1) {
        if (t < o) sh[t] += sh[t + o];
        __syncthreads();
    }
    if (t == 0) part[b] = sh[0];
}

__global__ void scan_tops_kernel(int* part, int nb) {
    __shared__ int sh[128];
    int t = threadIdx.x;
    int v = (t < nb) ? part[t] : 0;
    sh[t] = v;
    __syncthreads();
    for (int o = 1; o < 128; o <<= 1) {
        int add = (t >= o) ? sh[t - o] : 0;
        __syncthreads();
        sh[t] += add;
        __syncthreads();
    }
    if (t < nb) part[t] = sh[t] - v;   // exclusive
}

__global__ void scan_write_kernel(const int* __restrict__ cnt, const int* __restrict__ part,
                                  int* __restrict__ off, int n, int E) {
    __shared__ int sh[256];
    int b = blockIdx.x, t = threadIdx.x;
    int base = b * 1024 + t * 4;
    int c[4]; int s = 0;
    #pragma unroll
    for (int j = 0; j < 4; j++) {
        c[j] = (base + j < n) ? cnt[base + j] : 0;
        s += c[j];
    }
    int v = s;
    sh[t] = s;
    __syncthreads();
    for (int o = 1; o < 256; o <<= 1) {
        int add = (t >= o) ? sh[t - o] : 0;
        __syncthreads();
        sh[t] += add;
        __syncthreads();
    }
    int ex = sh[t] - v + part[b];
    #pragma unroll
    for (int j = 0; j < 4; j++) {
        if (base + j < n) { off[base + j] = ex; ex += c[j]; }
    }
    if (b == 0 && t == 0) off[n] = E;
}

__global__ void fill_kernel(const int* __restrict__ src, const int* __restrict__ dst,
                            const float* __restrict__ dinv,
                            const int* __restrict__ off, int* __restrict__ cur,
                            int2* __restrict__ edges, int E)
{
    int e = blockIdx.x * blockDim.x + threadIdx.x;
    if (e >= E) return;
    int s = src[e], d = dst[e];
    float w = dinv[s] * dinv[d];
    int pos = off[d] + atomicAdd(&cur[d], 1);
    edges[pos] = make_int2(s, __float_as_int(w));
}

// transpose + fp16-split W[K][128] -> Wh/Wl[128][K]
__global__ void wsplit_kernel(const float* __restrict__ W,
                              __half* __restrict__ Wh, __half* __restrict__ Wl, int K)
{
    int i = blockIdx.x * blockDim.x + threadIdx.x;
    if (i >= K * 128) return;
    int k = i >> 7, n = i & 127;
    float x = W[i];
    __half h = __float2half_rn(x);
    __half l = __float2half_rn(x - __half2float(h));
    Wh[(size_t)n * K + k] = h;
    Wl[(size_t)n * K + k] = l;
}

// ---------------- fp16-split tensor GEMM: C[M,128] = A[M,K]*W[K,128] --------
// BM=64, BN=128, BK=32 (2 x k16). 8 warps: 2 warp_m x 4 warp_n; each warp
// 32x32 output = 2 m16 x 4 n8 mma tiles. D += Ah*Bh + Ah*Bl + Al*Bh.
__device__ __forceinline__ void mma_f16(float* c, const uint32_t* a, const uint32_t* b) {
    asm volatile(
        "mma.sync.aligned.m16n8k16.row.col.f32.f16.f16.f32 "
        "{%0,%1,%2,%3}, {%4,%5,%6,%7}, {%8,%9}, {%0,%1,%2,%3};"
        : "+f"(c[0]), "+f"(c[1]), "+f"(c[2]), "+f"(c[3])
        : "r"(a[0]), "r"(a[1]), "r"(a[2]), "r"(a[3]), "r"(b[0]), "r"(b[1]));
}

#define ASTR 40   // halves per row (80B, 16B-aligned rows)
#define BSTR 40

__global__ __launch_bounds__(256) void gemm_fp16s_kernel(
    const float* __restrict__ A,
    const __half* __restrict__ Bh, const __half* __restrict__ Bl,
    float* __restrict__ C, __half* __restrict__ Ch, int M, int K)
{
    __shared__ __half Ash[64 * ASTR];
    __shared__ __half Asl[64 * ASTR];
    __shared__ __half Bsh[128 * BSTR];
    __shared__ __half Bsl[128 * BSTR];

    const int tid    = threadIdx.x;
    const int lane   = tid & 31;
    const int wid    = tid >> 5;
    const int warp_m = wid >> 2;    // 0..1
    const int warp_n = wid & 3;     // 0..3
    const int m0     = blockIdx.x * 64;
    const int g      = lane >> 2;   // 0..7
    const int t4     = lane & 3;    // 0..3

    float acc[2][4][4];
    #pragma unroll
    for (int i = 0; i < 2; i++)
        #pragma unroll
        for (int j = 0; j < 4; j++)
            #pragma unroll
            for (int k = 0; k < 4; k++) acc[i][j][k] = 0.f;

    for (int k0 = 0; k0 < K; k0 += 32) {
        // ---- A tile 64x32 fp32 -> split halves; 512 float4, 2 per thread ----
        #pragma unroll
        for (int i = 0; i < 2; i++) {
            int idx = tid + i * 256;
            int row = idx >> 3, c4 = idx & 7;
            float4 v = make_float4(0.f, 0.f, 0.f, 0.f);
            int grow = m0 + row;
            if (grow < M)
                v = *(const float4*)(A + (size_t)grow * K + k0 + c4 * 4);
            __half2 h01 = __floats2half2_rn(v.x, v.y);
            __half2 h23 = __floats2half2_rn(v.z, v.w);
            float2 f01 = __half22float2(h01);
            float2 f23 = __half22float2(h23);
            __half2 l01 = __floats2half2_rn(v.x - f01.x, v.y - f01.y);
            __half2 l23 = __floats2half2_rn(v.z - f23.x, v.w - f23.y);
            __half2* ph = (__half2*)&Ash[row * ASTR + c4 * 4];
            __half2* pl = (__half2*)&Asl[row * ASTR + c4 * 4];
            ph[0] = h01; ph[1] = h23;
            pl[0] = l01; pl[1] = l23;
        }
        // ---- B tile 128x32 halves (hi+lo); 512 int4 per split, 2/thread ----
        #pragma unroll
        for (int i = 0; i < 2; i++) {
            int idx = tid + i * 256;
            int row = idx >> 2, c8 = idx & 3;
            *(int4*)&Bsh[row * BSTR + c8 * 8] =
                *(const int4*)(Bh + (size_t)row * K + k0 + c8 * 8);
            *(int4*)&Bsl[row * BSTR + c8 * 8] =
                *(const int4*)(Bl + (size_t)row * K + k0 + c8 * 8);
        }
        __syncthreads();

        #pragma unroll
        for (int ks = 0; ks < 2; ks++) {
            const int kk = ks * 16;
            // A fragments (2 m16 tiles, hi+lo): half2 LDS only
            uint32_t ah[2][4], al[2][4];
            #pragma unroll
            for (int tm = 0; tm < 2; tm++) {
                int r = warp_m * 32 + tm * 16 + g;
                int c = kk + 2 * t4;
                ah[tm][0] = *(const uint32_t*)&Ash[r * ASTR + c];
                ah[tm][1] = *(const uint32_t*)&Ash[(r + 8) * ASTR + c];
                ah[tm][2] = *(const uint32_t*)&Ash[r * ASTR + c + 8];
                ah[tm][3] = *(const uint32_t*)&Ash[(r + 8) * ASTR + c + 8];
                al[tm][0] = *(const uint32_t*)&Asl[r * ASTR + c];
                al[tm][1] = *(const uint32_t*)&Asl[(r + 8) * ASTR + c];
                al[tm][2] = *(const uint32_t*)&Asl[r * ASTR + c + 8];
                al[tm][3] = *(const uint32_t*)&Asl[(r + 8) * ASTR + c + 8];
            }
            // B fragments (4 n8 tiles, hi+lo)
            uint32_t bh[4][2], bl[4][2];
            #pragma unroll
            for (int tn = 0; tn < 4; tn++) {
                int n = warp_n * 32 + tn * 8 + g;
                int c = kk + 2 * t4;
                bh[tn][0] = *(const uint32_t*)&Bsh[n * BSTR + c];
                bh[tn][1] = *(const uint32_t*)&Bsh[n * BSTR + c + 8];
                bl[tn][0] = *(const uint32_t*)&Bsl[n * BSTR + c];
                bl[tn][1] = *(const uint32_t*)&Bsl[n * BSTR + c + 8];
            }
            #pragma unroll
            for (int tm = 0; tm < 2; tm++)
                #pragma unroll
                for (int tn = 0; tn < 4; tn++) {
                    mma_f16(acc[tm][tn], ah[tm], bh[tn]);
                    mma_f16(acc[tm][tn], ah[tm], bl[tn]);
                    mma_f16(acc[tm][tn], al[tm], bh[tn]);
                }
        }
        __syncthreads();
    }

    // store C (fp32) + Ch (fp16 mirror)
    #pragma unroll
    for (int tm = 0; tm < 2; tm++)
        #pragma unroll
        for (int tn = 0; tn < 4; tn++) {
            int row0 = m0 + warp_m * 32 + tm * 16 + g;
            int coln = warp_n * 32 + tn * 8 + t4 * 2;
            if (row0 < M) {
                *(float2*)(C + (size_t)row0 * 128 + coln) =
                    make_float2(acc[tm][tn][0], acc[tm][tn][1]);
                *(__half2*)(Ch + (size_t)row0 * 128 + coln) =
                    __floats2half2_rn(acc[tm][tn][0], acc[tm][tn][1]);
            }
            if (row0 + 8 < M) {
                *(float2*)(C + (size_t)(row0 + 8) * 128 + coln) =
                    make_float2(acc[tm][tn][2], acc[tm][tn][3]);
                *(__half2*)(Ch + (size_t)(row0 + 8) * 128 + coln) =
                    __floats2half2_rn(acc[tm][tn][2], acc[tm][tn][3]);
            }
        }
}

// ---------------- gather-aggregate: out = relu(sum + h*dinv^2 + b) ----------
__global__ __launch_bounds__(256) void gather_kernel(
    const float* __restrict__ h, const __half* __restrict__ hh,
    const int2* __restrict__ edges,
    const int* __restrict__ off, const float* __restrict__ dinv,
    const float* __restrict__ bias, float* __restrict__ out, int N)
{
    int node = (blockIdx.x * blockDim.x + threadIdx.x) >> 5;
    int lane = threadIdx.x & 31;
    if (node >= N) return;

    float di = dinv[node];
    float dd = di * di;
    float4 hv = *(const float4*)(h + (size_t)node * CH + lane * 4);
    float4 bv = *(const float4*)(bias + lane * 4);
    float4 acc;
    acc.x = fmaf(hv.x, dd, bv.x);
    acc.y = fmaf(hv.y, dd, bv.y);
    acc.z = fmaf(hv.z, dd, bv.z);
    acc.w = fmaf(hv.w, dd, bv.w);

    int e  = __ldg(&off[node]);
    int e1 = __ldg(&off[node + 1]);

    for (; e + 3 < e1; e += 4) {
        int2 ev0 = __ldg(&edges[e]);
        int2 ev1 = __ldg(&edges[e + 1]);
        int2 ev2 = __ldg(&edges[e + 2]);
        int2 ev3 = __ldg(&edges[e + 3]);
        __half2 p0 = *(const __half2*)(hh + (size_t)ev0.x * CH + lane * 4);
        __half2 q0 = *(const __half2*)(hh + (size_t)ev0.x * CH + lane * 4 + 2);
        __half2 p1 = *(const __half2*)(hh + (size_t)ev1.x * CH + lane * 4);
        __half2 q1 = *(const __half2*)(hh + (size_t)ev1.x * CH + lane * 4 + 2);
        __half2 p2 = *(const __half2*)(hh + (size_t)ev2.x * CH + lane * 4);
        __half2 q2 = *(const __half2*)(hh + (size_t)ev2.x * CH + lane * 4 + 2);
        __half2 p3 = *(const __half2*)(hh + (size_t)ev3.x * CH + lane * 4);
        __half2 q3 = *(const __half2*)(hh + (size_t)ev3.x * CH + lane * 4 + 2);
        float w0 = __int_as_float(ev0.y);
        float w1 = __int_as_float(ev1.y);
        float w2 = __int_as_float(ev2.y);
        float w3 = __int_as_float(ev3.y);
        float2 a0 = __half22float2(p0), c0 = __half22float2(q0);
        float2 a1 = __half22float2(p1), c1 = __half22float2(q1);
        float2 a2 = __half22float2(p2), c2 = __half22float2(q2);
        float2 a3 = __half22float2(p3), c3 = __half22float2(q3);
        acc.x = fmaf(a0.x, w0, acc.x); acc.y = fmaf(a0.y, w0, acc.y);
        acc.z = fmaf(c0.x, w0, acc.z); acc.w = fmaf(c0.y, w0, acc.w);
        acc.x = fmaf(a1.x, w1, acc.x); acc.y = fmaf(a1.y, w1, acc.y);
        acc.z = fmaf(c1.x, w1, acc.z); acc.w = fmaf(c1.y, w1, acc.w);
        acc.x = fmaf(a2.x, w2, acc.x); acc.y = fmaf(a2.y, w2, acc.y);
        acc.z = fmaf(c2.x, w2, acc.z); acc.w = fmaf(c2.y, w2, acc.w);
        acc.x = fmaf(a3.x, w3, acc.x); acc.y = fmaf(a3.y, w3, acc.y);
        acc.z = fmaf(c3.x, w3, acc.z); acc.w = fmaf(c3.y, w3, acc.w);
    }
    for (; e < e1; e++) {
        int2 ev = __ldg(&edges[e]);
        __half2 p = *(const __half2*)(hh + (size_t)ev.x * CH + lane * 4);
        __half2 q = *(const __half2*)(hh + (size_t)ev.x * CH + lane * 4 + 2);
        float w = __int_as_float(ev.y);
        float2 a = __half22float2(p), c = __half22float2(q);
        acc.x = fmaf(a.x, w, acc.x); acc.y = fmaf(a.y, w, acc.y);
        acc.z = fmaf(c.x, w, acc.z); acc.w = fmaf(c.y, w, acc.w);
    }

    acc.x = fmaxf(acc.x, 0.f);
    acc.y = fmaxf(acc.y, 0.f);
    acc.z = fmaxf(acc.z, 0.f);
    acc.w = fmaxf(acc.w, 0.f);
    *(float4*)(out + (size_t)node * CH + lane * 4) = acc;
}

// ---------------- launch ----------------------------------------------------
extern "C" void kernel_launch(void* const* d_in, const int* in_sizes, int n_in,
                              void* d_out, int out_size)
{
    const float* x   = (const float*)d_in[0];
    const int*   ei  = (const int*)  d_in[1];
    const float* W1  = (const float*)d_in[2];
    const float* b1  = (const float*)d_in[3];
    const float* W2  = (const float*)d_in[4];
    const float* b2  = (const float*)d_in[5];
    float*       out = (float*)d_out;

    const int K1 = 256;
    const int N  = in_sizes[0] / K1;   // 50000
    const int E  = in_sizes[1] / 2;    // 1.6M
    const int* src = ei;
    const int* dst = ei + E;

    int *cnt, *cur, *off, *part;  float *dinv, *h, *out1;  int2* edges;  __half* hh;
    __half *w1h, *w1l, *w2h, *w2l;
    cudaGetSymbolAddress((void**)&cnt,   g_cnt);
    cudaGetSymbolAddress((void**)&cur,   g_cur);
    cudaGetSymbolAddress((void**)&off,   g_off);
    cudaGetSymbolAddress((void**)&part,  g_part);
    cudaGetSymbolAddress((void**)&dinv,  g_dinv);
    cudaGetSymbolAddress((void**)&edges, g_edges);
    cudaGetSymbolAddress((void**)&h,     g_h);
    cudaGetSymbolAddress((void**)&hh,    g_hh);
    cudaGetSymbolAddress((void**)&out1,  g_out1);
    cudaGetSymbolAddress((void**)&w1h,   g_w1h);
    cudaGetSymbolAddress((void**)&w1l,   g_w1l);
    cudaGetSymbolAddress((void**)&w2h,   g_w2h);
    cudaGetSymbolAddress((void**)&w2l,   g_w2l);

    const int T  = 256;
    const int nb = (N + 1023) / 1024;

    // --- split weights + build CSR by dst (once; reused by both layers) ---
    wsplit_kernel    <<<(K1 * 128 + T - 1) / T, T>>>(W1, w1h, w1l, K1);
    wsplit_kernel    <<<(128 * 128 + T - 1) / T, T>>>(W2, w2h, w2l, 128);
    zero_cnt_kernel  <<<(N + T - 1) / T, T>>>(cnt, cur, N);
    count_kernel     <<<(E + T - 1) / T, T>>>(dst, cnt, E);
    dinv_kernel      <<<(N + T - 1) / T, T>>>(cnt, dinv, N);
    scan_part_kernel <<<nb, 256>>>(cnt, part, N);
    scan_tops_kernel <<<1, 128>>>(part, nb);
    scan_write_kernel<<<nb, 256>>>(cnt, part, off, N, E);
    fill_kernel      <<<(E + T - 1) / T, T>>>(src, dst, dinv, off, cur, edges, E);

    int gemm_blocks   = (N + 63) / 64;
    int gather_blocks = (N + 7) / 8;

    // ---- layer 1 ----
    gemm_fp16s_kernel<<<gemm_blocks, 256>>>(x, w1h, w1l, h, hh, N, K1);
    gather_kernel    <<<gather_blocks, 256>>>(h, hh, edges, off, dinv, b1, out1, N);

    // ---- layer 2 ----
    gemm_fp16s_kernel<<<gemm_blocks, 256>>>(out1, w2h, w2l, h, hh, N, 128);
    gather_kernel    <<<gather_blocks, 256>>>(h, hh, edges, off, dinv, b2, out, N);
}